// round 16
// baseline (speedup 1.0000x reference)
#include <cuda_runtime.h>
#include <cuda_bf16.h>
#include <cstdint>
#include <mma.h>
#include <math.h>

using namespace nvcuda;

// ---------------------------------------------------------------------------
// Problem constants
// ---------------------------------------------------------------------------
#define NODES0 200000
#define NODES1 100000
#define NODES2 50000
#define NODES3 25000
#define FIN    256
#define DH     64
#define NHEAD  3
#define COUT   40
#define FMID   (NHEAD * DH)   // 192
#define COUT_PAD 48
#define EDGE_MAX 1000000

// ---------------------------------------------------------------------------
// Static device scratch
// ---------------------------------------------------------------------------
__device__ __align__(128) __nv_bfloat16 g_hbf[(size_t)NODES0 * FMID]; // L0/L1 features (bf16)
__device__ __align__(128) float g_hbuf[(size_t)NODES2 * COUT_PAD];    // L2 features (fp32)
__device__ __align__(128) float g_obuf[(size_t)NODES1 * FMID];
__device__ __align__(128) float g_el[(size_t)NODES0 * NHEAD];
__device__ __align__(128) float g_er[(size_t)NODES0 * NHEAD];
__device__ __align__(128) float g_alpha[(size_t)EDGE_MAX * NHEAD];
__device__ __align__(128) float g_W0r[FIN * FMID];
__device__ __align__(128) float g_W1r[FMID * FMID];
__device__ __align__(128) float g_W2r[FMID * COUT];
__device__ int g_rp0[NODES1 + 1];
__device__ int g_rp1[NODES2 + 1];
__device__ int g_rp2[NODES3 + 1];

// ---------------------------------------------------------------------------
// cp.async helpers
// ---------------------------------------------------------------------------
__device__ __forceinline__ unsigned int smem_u32(const void* p) {
    return (unsigned int)__cvta_generic_to_shared(p);
}
__device__ __forceinline__ void cp16(unsigned int d, const void* s) {
    asm volatile("cp.async.cg.shared.global [%0], [%1], 16;" :: "r"(d), "l"(s));
}
#define CP_COMMIT() asm volatile("cp.async.commit_group;")
#define CP_WAIT0()  asm volatile("cp.async.wait_group 0;")

// ---------------------------------------------------------------------------
// Pre-round weight matrices to tf32-representable fp32 (RN), once per call.
// ---------------------------------------------------------------------------
__global__ void round_w_kernel(const float* __restrict__ W0,
                               const float* __restrict__ W1,
                               const float* __restrict__ W2,
                               float* __restrict__ W0r,
                               float* __restrict__ W1r,
                               float* __restrict__ W2r)
{
    int i = blockIdx.x * blockDim.x + threadIdx.x;
    if (i < FIN * FMID)  W0r[i] = wmma::__float_to_tf32(W0[i]);
    if (i < FMID * FMID) W1r[i] = wmma::__float_to_tf32(W1[i]);
    if (i < FMID * COUT) W2r[i] = wmma::__float_to_tf32(W2[i]);
}

// ---------------------------------------------------------------------------
// All three row_ptr arrays in ONE launch (edge-diff scatter, thread/edge).
// ---------------------------------------------------------------------------
__device__ __forceinline__ void rp_scatter(const int* __restrict__ dst, int E,
                                           int n_dst, int* __restrict__ rp, int e)
{
    int d1 = dst[e];
    int d0 = (e == 0) ? -1 : dst[e - 1];
    for (int d = d0 + 1; d <= d1; d++) rp[d] = e;
    if (e == E - 1)
        for (int d = d1 + 1; d <= n_dst; d++) rp[d] = E;
}

__global__ void rowptr_all(const int* __restrict__ dst0, int E0,
                           const int* __restrict__ dst1, int E1,
                           const int* __restrict__ dst2, int E2,
                           int* __restrict__ rp0, int* __restrict__ rp1,
                           int* __restrict__ rp2)
{
    int t = blockIdx.x * blockDim.x + threadIdx.x;
    if (t < E0) {
        rp_scatter(dst0, E0, NODES1, rp0, t);
    } else if (t < E0 + E1) {
        rp_scatter(dst1, E1, NODES2, rp1, t - E0);
    } else if (t < E0 + E1 + E2) {
        rp_scatter(dst2, E2, NODES3, rp2, t - E0 - E1);
    }
}

// ---------------------------------------------------------------------------
// TF32 wmma GEMM, full-N tile, 2-stage cp.async, FUSED el/er epilogue.
// STOREBF: C is written as bf16 (from the smem staging the epilogue already
// does for el/er) instead of fp32. Each lane stores 8 bf16 = 16B; a fragment
// row = exactly one 32B DRAM sector, so nothing is wasted.
// ---------------------------------------------------------------------------
template <int BN_, int WM_, int WN_, bool CONVA, int DHEAD, int HEADS, bool STOREBF>
__global__ __launch_bounds__(256) void gemm_fused(
    const float* __restrict__ A, const float* __restrict__ B,
    float* __restrict__ C, __nv_bfloat16* __restrict__ Cbf,
    int M, int N, int K, int ldc,
    const float* __restrict__ alv, const float* __restrict__ arv,
    float* __restrict__ el, float* __restrict__ er)
{
    constexpr int BM = 128, BK = 16;
    constexpr int LDA = BK + 4;             // 20
    constexpr int LDB = BN_ + 4;            // 196 / 52
    constexpr int WTM = BM / WM_;           // 32 / 16
    constexpr int WTN = BN_ / WN_;          // 96 / 48
    constexpr int MF  = WTM / 16;           // 2 / 1
    constexpr int NF  = WTN / 16;           // 6 / 3
    constexpr int BE4 = BK * BN_ / 4;
    constexpr int POOL = 2 * BM * LDA + 2 * BK * LDB;

    __shared__ float pool[POOL];
    float* Asp[2] = { pool, pool + BM * LDA };
    float* Bsp[2] = { pool + 2 * BM * LDA, pool + 2 * BM * LDA + BK * LDB };

    const int tid  = threadIdx.x;
    const int warp = tid >> 5;
    const int lane = tid & 31;
    const int wm   = warp / WN_;
    const int wn   = warp % WN_;
    const int brow = blockIdx.x * BM;
    const int T    = K / BK;

    wmma::fragment<wmma::accumulator, 16, 16, 8, float> acc[MF][NF];
#pragma unroll
    for (int i = 0; i < MF; i++)
#pragma unroll
        for (int j = 0; j < NF; j++) wmma::fill_fragment(acc[i][j], 0.0f);

#define PREFETCH(t, st)                                                        \
    do {                                                                       \
        int k0 = (t) * BK;                                                     \
        _Pragma("unroll")                                                      \
        for (int i = 0; i < 2; i++) {                                          \
            int idx = tid + i * 256;                                           \
            int r   = idx >> 2;                                                \
            int c4  = idx & 3;                                                 \
            int grow = brow + r;                                               \
            if (grow >= M) grow = M - 1;                                       \
            cp16(smem_u32(&Asp[st][r * LDA + c4 * 4]),                         \
                 &A[(size_t)grow * K + k0 + c4 * 4]);                          \
        }                                                                      \
        _Pragma("unroll")                                                      \
        for (int i = 0; i < (BE4 + 255) / 256; i++) {                          \
            int idx = tid + i * 256;                                           \
            if (idx < BE4) {                                                   \
                int r  = idx / (BN_ / 4);                                      \
                int c4 = idx % (BN_ / 4);                                      \
                int gc = c4 * 4;                                               \
                if (gc + 4 > N) gc = N - 4;                                    \
                cp16(smem_u32(&Bsp[st][r * LDB + c4 * 4]),                     \
                     &B[(size_t)(k0 + r) * N + gc]);                           \
            }                                                                  \
        }                                                                      \
        CP_COMMIT();                                                           \
    } while (0)

    PREFETCH(0, 0);

    for (int t = 0; t < T; t++) {
        CP_WAIT0();
        __syncthreads();
        if (t + 1 < T)
            PREFETCH(t + 1, (t + 1) & 1);
        const int st = t & 1;
#pragma unroll
        for (int kk = 0; kk < BK; kk += 8) {
            wmma::fragment<wmma::matrix_a, 16, 16, 8, wmma::precision::tf32, wmma::row_major> a[MF];
            wmma::fragment<wmma::matrix_b, 16, 16, 8, wmma::precision::tf32, wmma::row_major> b[NF];
#pragma unroll
            for (int i = 0; i < MF; i++) {
                wmma::load_matrix_sync(a[i], &Asp[st][(wm * WTM + i * 16) * LDA + kk], LDA);
                if (CONVA) {
#pragma unroll
                    for (int e = 0; e < a[i].num_elements; e++)
                        a[i].x[e] = wmma::__float_to_tf32(a[i].x[e]);
                }
            }
#pragma unroll
            for (int j = 0; j < NF; j++)
                wmma::load_matrix_sync(b[j], &Bsp[st][kk * LDB + wn * WTN + j * 16], LDB);
#pragma unroll
            for (int i = 0; i < MF; i++)
#pragma unroll
                for (int j = 0; j < NF; j++)
                    wmma::mma_sync(acc[i][j], a[i], b[j], acc[i][j]);
        }
        __syncthreads();
    }
#undef PREFETCH

    // ---- Epilogue: C store (bf16 or fp32) + fused el/er from registers ----
    float* stage = pool;                    // 8 warps * 16*20 = 2560
    float* alsm  = pool + 8 * 16 * 20;      // BN_
    float* arsm  = alsm + BN_;              // BN_
    float* bufl  = arsm + BN_;              // BM
    float* bufr  = bufl + BM;               // BM

    for (int i = tid; i < BN_; i += 256) {
        alsm[i] = (i < N) ? alv[i] : 0.f;
        arsm[i] = (i < N) ? arv[i] : 0.f;
    }
    __syncthreads();

    const int row_l = lane & 15;
    const int half  = lane >> 4;
    float* mystage = stage + warp * (16 * 20);

    float hel[MF][HEADS], her[MF][HEADS];
#pragma unroll
    for (int i = 0; i < MF; i++)
#pragma unroll
        for (int h = 0; h < HEADS; h++) { hel[i][h] = 0.f; her[i][h] = 0.f; }

#pragma unroll
    for (int i = 0; i < MF; i++) {
        const int row0 = brow + wm * WTM + i * 16;
#pragma unroll
        for (int j = 0; j < NF; j++) {
            const int col0 = wn * WTN + j * 16;
            const bool inb = (row0 + 16 <= M) && (col0 + 16 <= ldc);
            if (!STOREBF && inb)
                wmma::store_matrix_sync(&C[(size_t)row0 * ldc + col0], acc[i][j],
                                        ldc, wmma::mem_row_major);
            wmma::store_matrix_sync(mystage, acc[i][j], 20, wmma::mem_row_major);
            __syncwarp();
            float f[8];
            float sl = 0.f, sr = 0.f;
#pragma unroll
            for (int c = 0; c < 8; c++) {
                f[c] = mystage[row_l * 20 + half * 8 + c];
                sl = fmaf(f[c], alsm[col0 + half * 8 + c], sl);
                sr = fmaf(f[c], arsm[col0 + half * 8 + c], sr);
            }
            if (STOREBF && inb) {
                __nv_bfloat162 p[4];
#pragma unroll
                for (int c = 0; c < 4; c++)
                    p[c] = __nv_bfloat162(__float2bfloat16_rn(f[2 * c]),
                                          __float2bfloat16_rn(f[2 * c + 1]));
                *(uint4*)&Cbf[(size_t)(row0 + row_l) * ldc + col0 + half * 8] =
                    *(const uint4*)p;
            }
            __syncwarp();
            const int hd = col0 / DHEAD;
#pragma unroll
            for (int h = 0; h < HEADS; h++)
                if (hd == h) { hel[i][h] += sl; her[i][h] += sr; }
        }
    }

#pragma unroll
    for (int i = 0; i < MF; i++)
#pragma unroll
        for (int h = 0; h < HEADS; h++) {
            hel[i][h] += __shfl_xor_sync(0xffffffffu, hel[i][h], 16);
            her[i][h] += __shfl_xor_sync(0xffffffffu, her[i][h], 16);
        }

#pragma unroll
    for (int i = 0; i < MF; i++) {
        const int grow = brow + wm * WTM + i * 16 + row_l;
        const bool w = (half == 0) && (grow < M);
        if (WN_ == 1) {
            if (w) {
#pragma unroll
                for (int h = 0; h < HEADS; h++) {
                    el[grow * HEADS + h] = hel[i][h];
                    er[grow * HEADS + h] = her[i][h];
                }
            }
        } else {
            if (w && wn == 0) {
                el[grow * HEADS + 0] = hel[i][0];
                er[grow * HEADS + 0] = her[i][0];
                bufl[grow - brow] = hel[i][1];
                bufr[grow - brow] = her[i][1];
            }
        }
    }
    if (WN_ > 1) {
        __syncthreads();
#pragma unroll
        for (int i = 0; i < MF; i++) {
            const int grow = brow + wm * WTM + i * 16 + row_l;
            const bool w = (half == 0) && (grow < M);
            if (w && wn == 1) {
                el[grow * HEADS + 1] = bufl[grow - brow] + hel[i][1];
                er[grow * HEADS + 1] = bufr[grow - brow] + her[i][1];
                el[grow * HEADS + 2] = hel[i][2];
                er[grow * HEADS + 2] = her[i][2];
            }
        }
    }
}

// ---------------------------------------------------------------------------
// gat_softmax: warp per dst. Max-shifted softmax; writes normalized alpha.
// ---------------------------------------------------------------------------
__device__ __forceinline__ float leaky02(float v) {
    return v > 0.f ? v : 0.2f * v;
}

template <int H>
__global__ __launch_bounds__(256) void gat_softmax(
    const float* __restrict__ el, const float* __restrict__ er,
    const int* __restrict__ src, const int* __restrict__ rp,
    float* __restrict__ alpha, int n_dst)
{
    const int gw = (blockIdx.x * blockDim.x + threadIdx.x) >> 5;
    if (gw >= n_dst) return;
    const int lane = threadIdx.x & 31;
    const int d = gw;
    const int start = rp[d];
    const int end   = rp[d + 1];

    float er_d[H];
#pragma unroll
    for (int hh = 0; hh < H; hh++) er_d[hh] = er[d * H + hh];

    float v0[H], m[H];
#pragma unroll
    for (int hh = 0; hh < H; hh++) { v0[hh] = 0.f; m[hh] = -INFINITY; }
    {
        int e = start + lane;
        if (e < end) {
            int sn = src[e];
#pragma unroll
            for (int hh = 0; hh < H; hh++) {
                v0[hh] = leaky02(el[sn * H + hh] + er_d[hh]);
                m[hh]  = v0[hh];
            }
        }
    }
    for (int e = start + 32 + lane; e < end; e += 32) {
        int sn = src[e];
#pragma unroll
        for (int hh = 0; hh < H; hh++)
            m[hh] = fmaxf(m[hh], leaky02(el[sn * H + hh] + er_d[hh]));
    }
#pragma unroll
    for (int hh = 0; hh < H; hh++)
#pragma unroll
        for (int o = 16; o; o >>= 1)
            m[hh] = fmaxf(m[hh], __shfl_xor_sync(0xffffffffu, m[hh], o));

    float w0[H], s[H];
#pragma unroll
    for (int hh = 0; hh < H; hh++) { s[hh] = 0.f; w0[hh] = 0.f; }
    if (start + lane < end) {
#pragma unroll
        for (int hh = 0; hh < H; hh++) {
            w0[hh] = __expf(v0[hh] - m[hh]);
            s[hh]  = w0[hh];
        }
    }
    for (int e = start + 32 + lane; e < end; e += 32) {
        int sn = src[e];
#pragma unroll
        for (int hh = 0; hh < H; hh++)
            s[hh] += __expf(leaky02(el[sn * H + hh] + er_d[hh]) - m[hh]);
    }
#pragma unroll
    for (int hh = 0; hh < H; hh++)
#pragma unroll
        for (int o = 16; o; o >>= 1)
            s[hh] += __shfl_xor_sync(0xffffffffu, s[hh], o);
    float inv[H];
#pragma unroll
    for (int hh = 0; hh < H; hh++)
        inv[hh] = (s[hh] > 0.f) ? 1.0f / s[hh] : 0.f;

    if (start + lane < end) {
        int e = start + lane;
#pragma unroll
        for (int hh = 0; hh < H; hh++)
            alpha[(size_t)e * H + hh] = w0[hh] * inv[hh];
    }
    for (int e = start + 32 + lane; e < end; e += 32) {
        int sn = src[e];
#pragma unroll
        for (int hh = 0; hh < H; hh++)
            alpha[(size_t)e * H + hh] =
                __expf(leaky02(el[sn * H + hh] + er_d[hh]) - m[hh]) * inv[hh];
    }
}

// ---------------------------------------------------------------------------
// gat_gather_bf: warp per dst over bf16 features (H=3, D=64, stride 192).
// Lane j<24 owns one 8-element (16B) chunk; per edge loads HALVE vs fp32.
// Unroll 2 edges (proven sweet spot). Output fp32 + tf32 RN round (feeds
// next GEMM as A).
// ---------------------------------------------------------------------------
template <bool RELU>
__global__ __launch_bounds__(256) void gat_gather_bf(
    const __nv_bfloat16* __restrict__ h, const float* __restrict__ alpha,
    const int* __restrict__ src, const int* __restrict__ rp,
    float* __restrict__ out, int n_dst)
{
    constexpr int HD = 192;
    constexpr int CH = HD / 8;    // 24 chunks

    const int gw = (blockIdx.x * blockDim.x + threadIdx.x) >> 5;
    if (gw >= n_dst) return;
    const int lane = threadIdx.x & 31;
    const int d = gw;
    const int start = rp[d];
    const int end   = rp[d + 1];

    const int j    = lane;
    const int head = (j < CH) ? (j * 8) / DH : 0;
    const bool act = (j < CH);

    float acc[8];
#pragma unroll
    for (int q = 0; q < 8; q++) acc[q] = 0.f;

    int e = start;
    for (; e + 2 <= end; e += 2) {
        const int sn0 = __ldg(&src[e]);
        const int sn1 = __ldg(&src[e + 1]);
        if (act) {
            const float a0 = __ldg(&alpha[(size_t)e * NHEAD + head]);
            const float a1 = __ldg(&alpha[(size_t)(e + 1) * NHEAD + head]);
            const uint4 u0 = *((const uint4*)(h + (size_t)sn0 * HD) + j);
            const uint4 u1 = *((const uint4*)(h + (size_t)sn1 * HD) + j);
            const __nv_bfloat162* p0 = (const __nv_bfloat162*)&u0;
            const __nv_bfloat162* p1 = (const __nv_bfloat162*)&u1;
#pragma unroll
            for (int k = 0; k < 4; k++) {
                float2 f0 = __bfloat1622float2(p0[k]);
                float2 f1 = __bfloat1622float2(p1[k]);
                acc[2 * k]     = fmaf(f0.x, a0, acc[2 * k]);
                acc[2 * k + 1] = fmaf(f0.y, a0, acc[2 * k + 1]);
                acc[2 * k]     = fmaf(f1.x, a1, acc[2 * k]);
                acc[2 * k + 1] = fmaf(f1.y, a1, acc[2 * k + 1]);
            }
        }
    }
    if (e < end) {
        const int sn0 = __ldg(&src[e]);
        if (act) {
            const float a0 = __ldg(&alpha[(size_t)e * NHEAD + head]);
            const uint4 u0 = *((const uint4*)(h + (size_t)sn0 * HD) + j);
            const __nv_bfloat162* p0 = (const __nv_bfloat162*)&u0;
#pragma unroll
            for (int k = 0; k < 4; k++) {
                float2 f0 = __bfloat1622float2(p0[k]);
                acc[2 * k]     = fmaf(f0.x, a0, acc[2 * k]);
                acc[2 * k + 1] = fmaf(f0.y, a0, acc[2 * k + 1]);
            }
        }
    }

    if (act) {
#pragma unroll
        for (int q = 0; q < 8; q++) {
            if (RELU) acc[q] = fmaxf(acc[q], 0.f);
            acc[q] = wmma::__float_to_tf32(acc[q]);   // feeds next GEMM A
        }
        float4* op = (float4*)(out + (size_t)d * HD + j * 8);
        op[0] = make_float4(acc[0], acc[1], acc[2], acc[3]);
        op[1] = make_float4(acc[4], acc[5], acc[6], acc[7]);
    }
}

// ---------------------------------------------------------------------------
// gat_gather (fp32): layer 2 only (H=1, D=40, stride 48). R10-proven.
// ---------------------------------------------------------------------------
template <int H, int D, int STRIDE, bool RELU, bool TF32OUT>
__global__ __launch_bounds__(256) void gat_gather(
    const float* __restrict__ h, const float* __restrict__ alpha,
    const int* __restrict__ src, const int* __restrict__ rp,
    float* __restrict__ out, int n_dst)
{
    constexpr int HD  = H * D;
    constexpr int HD4 = HD / 4;
    constexpr int NJ  = (HD4 + 31) / 32;

    const int gw = (blockIdx.x * blockDim.x + threadIdx.x) >> 5;
    if (gw >= n_dst) return;
    const int lane = threadIdx.x & 31;
    const int d = gw;
    const int start = rp[d];
    const int end   = rp[d + 1];

    int headj[NJ];
#pragma unroll
    for (int jj = 0; jj < NJ; jj++) {
        int j = lane + jj * 32;
        int hh = (j * 4) / D;
        headj[jj] = hh < H ? hh : H - 1;
    }

    float4 facc[NJ];
#pragma unroll
    for (int jj = 0; jj < NJ; jj++) facc[jj] = make_float4(0.f, 0.f, 0.f, 0.f);

    int e = start;
    for (; e + 2 <= end; e += 2) {
        const int sn0 = __ldg(&src[e]);
        const int sn1 = __ldg(&src[e + 1]);
        float a0[NJ], a1[NJ];
#pragma unroll
        for (int jj = 0; jj < NJ; jj++) {
            a0[jj] = __ldg(&alpha[(size_t)e * H + headj[jj]]);
            a1[jj] = __ldg(&alpha[(size_t)(e + 1) * H + headj[jj]]);
        }
        const float4* hp0 = (const float4*)(h + (size_t)sn0 * STRIDE);
        const float4* hp1 = (const float4*)(h + (size_t)sn1 * STRIDE);
#pragma unroll
        for (int jj = 0; jj < NJ; jj++) {
            int j = lane + jj * 32;
            if (j < HD4) {
                float4 v0 = hp0[j];
                float4 v1 = hp1[j];
                facc[jj].x = fmaf(v0.x, a0[jj], facc[jj].x);
                facc[jj].y = fmaf(v0.y, a0[jj], facc[jj].y);
                facc[jj].z = fmaf(v0.z, a0[jj], facc[jj].z);
                facc[jj].w = fmaf(v0.w, a0[jj], facc[jj].w);
                facc[jj].x = fmaf(v1.x, a1[jj], facc[jj].x);
                facc[jj].y = fmaf(v1.y, a1[jj], facc[jj].y);
                facc[jj].z = fmaf(v1.z, a1[jj], facc[jj].z);
                facc[jj].w = fmaf(v1.w, a1[jj], facc[jj].w);
            }
        }
    }
    if (e < end) {
        const int sn0 = __ldg(&src[e]);
        const float4* hp0 = (const float4*)(h + (size_t)sn0 * STRIDE);
#pragma unroll
        for (int jj = 0; jj < NJ; jj++) {
            int j = lane + jj * 32;
            if (j < HD4) {
                float a = __ldg(&alpha[(size_t)e * H + headj[jj]]);
                float4 v = hp0[j];
                facc[jj].x = fmaf(v.x, a, facc[jj].x);
                facc[jj].y = fmaf(v.y, a, facc[jj].y);
                facc[jj].z = fmaf(v.z, a, facc[jj].z);
                facc[jj].w = fmaf(v.w, a, facc[jj].w);
            }
        }
    }

#pragma unroll
    for (int jj = 0; jj < NJ; jj++) {
        int j = lane + jj * 32;
        if (j < HD4) {
            float4 r = facc[jj];
            if (RELU) {
                r.x = fmaxf(r.x, 0.f); r.y = fmaxf(r.y, 0.f);
                r.z = fmaxf(r.z, 0.f); r.w = fmaxf(r.w, 0.f);
            }
            if (TF32OUT) {
                r.x = wmma::__float_to_tf32(r.x);
                r.y = wmma::__float_to_tf32(r.y);
                r.z = wmma::__float_to_tf32(r.z);
                r.w = wmma::__float_to_tf32(r.w);
            }
            ((float4*)(out + (size_t)d * HD))[j] = r;
        }
    }
}

// ---------------------------------------------------------------------------
// Launch
// ---------------------------------------------------------------------------
static inline int ceil_div(int a, int b) { return (a + b - 1) / b; }

extern "C" void kernel_launch(void* const* d_in, const int* in_sizes, int n_in,
                              void* d_out, int out_size)
{
    const float* x    = (const float*)d_in[0];
    const int*   src0 = (const int*)  d_in[1];
    const int*   dst0 = (const int*)  d_in[2];
    const int*   src1 = (const int*)  d_in[3];
    const int*   dst1 = (const int*)  d_in[4];
    const int*   src2 = (const int*)  d_in[5];
    const int*   dst2 = (const int*)  d_in[6];
    const float* W0   = (const float*)d_in[7];
    const float* al0  = (const float*)d_in[8];
    const float* ar0  = (const float*)d_in[9];
    const float* W1   = (const float*)d_in[10];
    const float* al1  = (const float*)d_in[11];
    const float* ar1  = (const float*)d_in[12];
    const float* W2   = (const float*)d_in[13];
    const float* al2  = (const float*)d_in[14];
    const float* ar2  = (const float*)d_in[15];
    float* out = (float*)d_out;

    const int E0 = in_sizes[1];
    const int E1 = in_sizes[3];
    const int E2 = in_sizes[5];

    float *hbuf, *obuf, *el, *er, *alpha, *w0r, *w1r, *w2r;
    __nv_bfloat16* hbf;
    int *rp0, *rp1, *rp2;
    cudaGetSymbolAddress((void**)&hbf,   g_hbf);
    cudaGetSymbolAddress((void**)&hbuf,  g_hbuf);
    cudaGetSymbolAddress((void**)&obuf,  g_obuf);
    cudaGetSymbolAddress((void**)&el,    g_el);
    cudaGetSymbolAddress((void**)&er,    g_er);
    cudaGetSymbolAddress((void**)&alpha, g_alpha);
    cudaGetSymbolAddress((void**)&w0r,   g_W0r);
    cudaGetSymbolAddress((void**)&w1r,   g_W1r);
    cudaGetSymbolAddress((void**)&w2r,   g_W2r);
    cudaGetSymbolAddress((void**)&rp0,   g_rp0);
    cudaGetSymbolAddress((void**)&rp1,   g_rp1);
    cudaGetSymbolAddress((void**)&rp2,   g_rp2);

    round_w_kernel<<<ceil_div(FIN * FMID, 256), 256>>>(W0, W1, W2, w0r, w1r, w2r);
    rowptr_all<<<ceil_div(E0 + E1 + E2, 256), 256>>>(dst0, E0, dst1, E1, dst2, E2,
                                                     rp0, rp1, rp2);

    // ---------------- Layer 0: 200000x256 @ 256x192, bf16 features -------
    {
        gemm_fused<FMID, 4, 2, true, DH, NHEAD, true><<<ceil_div(NODES0, 128), 256>>>(
            x, w0r, nullptr, hbf, NODES0, FMID, FIN, FMID, al0, ar0, el, er);
        gat_softmax<NHEAD><<<ceil_div(NODES1, 8), 256>>>(el, er, src0, rp0, alpha, NODES1);
        gat_gather_bf<true><<<ceil_div(NODES1, 8), 256>>>(
            hbf, alpha, src0, rp0, obuf, NODES1);
    }

    // ---------------- Layer 1: 100000x192 @ 192x192, bf16 features -------
    {
        gemm_fused<FMID, 4, 2, false, DH, NHEAD, true><<<ceil_div(NODES1, 128), 256>>>(
            obuf, w1r, nullptr, hbf, NODES1, FMID, FMID, FMID, al1, ar1, el, er);
        gat_softmax<NHEAD><<<ceil_div(NODES2, 8), 256>>>(el, er, src1, rp1, alpha, NODES2);
        gat_gather_bf<true><<<ceil_div(NODES2, 8), 256>>>(
            hbf, alpha, src1, rp1, obuf, NODES2);
    }

    // ---------------- Layer 2: 50000x192 @ 192x40 (fp32, padded ldc=48) --
    {
        gemm_fused<COUT_PAD, 8, 1, false, 64, 1, false><<<ceil_div(NODES2, 128), 256>>>(
            obuf, w2r, hbuf, nullptr, NODES2, COUT, FMID, COUT_PAD, al2, ar2, el, er);
        gat_softmax<1><<<ceil_div(NODES3, 8), 256>>>(el, er, src2, rp2, alpha, NODES3);
        gat_gather<1, COUT, COUT_PAD, false, false><<<ceil_div(NODES3, 8), 256>>>(
            hbuf, alpha, src2, rp2, out, NODES3);
    }
}

// round 17
// speedup vs baseline: 1.5142x; 1.5142x over previous
#include <cuda_runtime.h>
#include <cuda_bf16.h>
#include <cstdint>
#include <mma.h>
#include <math.h>

using namespace nvcuda;

// ---------------------------------------------------------------------------
// Problem constants
// ---------------------------------------------------------------------------
#define NODES0 200000
#define NODES1 100000
#define NODES2 50000
#define NODES3 25000
#define FIN    256
#define DH     64
#define NHEAD  3
#define COUT   40
#define FMID   (NHEAD * DH)   // 192
#define COUT_PAD 48
#define EDGE_MAX 1000000

// ---------------------------------------------------------------------------
// Static device scratch
// ---------------------------------------------------------------------------
__device__ __align__(128) __nv_bfloat16 g_hbf[(size_t)NODES0 * FMID]; // L0/L1 features (bf16)
__device__ __align__(128) float g_hbuf[(size_t)NODES2 * COUT_PAD];    // L2 features (fp32)
__device__ __align__(128) float g_obuf[(size_t)NODES1 * FMID];
__device__ __align__(128) float g_el[(size_t)NODES0 * NHEAD];
__device__ __align__(128) float g_er[(size_t)NODES0 * NHEAD];
__device__ __align__(128) float g_alpha[(size_t)EDGE_MAX * NHEAD];
__device__ __align__(128) float g_W0r[FIN * FMID];
__device__ __align__(128) float g_W1r[FMID * FMID];
__device__ __align__(128) float g_W2r[FMID * COUT];
__device__ int g_rp0[NODES1 + 1];
__device__ int g_rp1[NODES2 + 1];
__device__ int g_rp2[NODES3 + 1];

// ---------------------------------------------------------------------------
// cp.async helpers
// ---------------------------------------------------------------------------
__device__ __forceinline__ unsigned int smem_u32(const void* p) {
    return (unsigned int)__cvta_generic_to_shared(p);
}
__device__ __forceinline__ void cp16(unsigned int d, const void* s) {
    asm volatile("cp.async.cg.shared.global [%0], [%1], 16;" :: "r"(d), "l"(s));
}
#define CP_COMMIT() asm volatile("cp.async.commit_group;")
#define CP_WAIT0()  asm volatile("cp.async.wait_group 0;")

// ---------------------------------------------------------------------------
// Pre-round weight matrices to tf32-representable fp32 (RN), once per call.
// ---------------------------------------------------------------------------
__global__ void round_w_kernel(const float* __restrict__ W0,
                               const float* __restrict__ W1,
                               const float* __restrict__ W2,
                               float* __restrict__ W0r,
                               float* __restrict__ W1r,
                               float* __restrict__ W2r)
{
    int i = blockIdx.x * blockDim.x + threadIdx.x;
    if (i < FIN * FMID)  W0r[i] = wmma::__float_to_tf32(W0[i]);
    if (i < FMID * FMID) W1r[i] = wmma::__float_to_tf32(W1[i]);
    if (i < FMID * COUT) W2r[i] = wmma::__float_to_tf32(W2[i]);
}

// ---------------------------------------------------------------------------
// All three row_ptr arrays in ONE launch (edge-diff scatter, thread/edge).
// ---------------------------------------------------------------------------
__device__ __forceinline__ void rp_scatter(const int* __restrict__ dst, int E,
                                           int n_dst, int* __restrict__ rp, int e)
{
    int d1 = dst[e];
    int d0 = (e == 0) ? -1 : dst[e - 1];
    for (int d = d0 + 1; d <= d1; d++) rp[d] = e;
    if (e == E - 1)
        for (int d = d1 + 1; d <= n_dst; d++) rp[d] = E;
}

__global__ void rowptr_all(const int* __restrict__ dst0, int E0,
                           const int* __restrict__ dst1, int E1,
                           const int* __restrict__ dst2, int E2,
                           int* __restrict__ rp0, int* __restrict__ rp1,
                           int* __restrict__ rp2)
{
    int t = blockIdx.x * blockDim.x + threadIdx.x;
    if (t < E0) {
        rp_scatter(dst0, E0, NODES1, rp0, t);
    } else if (t < E0 + E1) {
        rp_scatter(dst1, E1, NODES2, rp1, t - E0);
    } else if (t < E0 + E1 + E2) {
        rp_scatter(dst2, E2, NODES3, rp2, t - E0 - E1);
    }
}

// ---------------------------------------------------------------------------
// TF32 wmma GEMM, full-N tile, 2-stage cp.async, FUSED el/er epilogue.
// STOREBF: C written as bf16 from the smem staging the epilogue already
// does for el/er. Each lane stores 8 bf16 = 16B; a fragment row = one full
// 32B DRAM sector.
// ---------------------------------------------------------------------------
template <int BN_, int WM_, int WN_, bool CONVA, int DHEAD, int HEADS, bool STOREBF>
__global__ __launch_bounds__(256) void gemm_fused(
    const float* __restrict__ A, const float* __restrict__ B,
    float* __restrict__ C, __nv_bfloat16* __restrict__ Cbf,
    int M, int N, int K, int ldc,
    const float* __restrict__ alv, const float* __restrict__ arv,
    float* __restrict__ el, float* __restrict__ er)
{
    constexpr int BM = 128, BK = 16;
    constexpr int LDA = BK + 4;             // 20
    constexpr int LDB = BN_ + 4;            // 196 / 52
    constexpr int WTM = BM / WM_;           // 32 / 16
    constexpr int WTN = BN_ / WN_;          // 96 / 48
    constexpr int MF  = WTM / 16;           // 2 / 1
    constexpr int NF  = WTN / 16;           // 6 / 3
    constexpr int BE4 = BK * BN_ / 4;
    constexpr int POOL = 2 * BM * LDA + 2 * BK * LDB;

    __shared__ float pool[POOL];
    float* Asp[2] = { pool, pool + BM * LDA };
    float* Bsp[2] = { pool + 2 * BM * LDA, pool + 2 * BM * LDA + BK * LDB };

    const int tid  = threadIdx.x;
    const int warp = tid >> 5;
    const int lane = tid & 31;
    const int wm   = warp / WN_;
    const int wn   = warp % WN_;
    const int brow = blockIdx.x * BM;
    const int T    = K / BK;

    wmma::fragment<wmma::accumulator, 16, 16, 8, float> acc[MF][NF];
#pragma unroll
    for (int i = 0; i < MF; i++)
#pragma unroll
        for (int j = 0; j < NF; j++) wmma::fill_fragment(acc[i][j], 0.0f);

#define PREFETCH(t, st)                                                        \
    do {                                                                       \
        int k0 = (t) * BK;                                                     \
        _Pragma("unroll")                                                      \
        for (int i = 0; i < 2; i++) {                                          \
            int idx = tid + i * 256;                                           \
            int r   = idx >> 2;                                                \
            int c4  = idx & 3;                                                 \
            int grow = brow + r;                                               \
            if (grow >= M) grow = M - 1;                                       \
            cp16(smem_u32(&Asp[st][r * LDA + c4 * 4]),                         \
                 &A[(size_t)grow * K + k0 + c4 * 4]);                          \
        }                                                                      \
        _Pragma("unroll")                                                      \
        for (int i = 0; i < (BE4 + 255) / 256; i++) {                          \
            int idx = tid + i * 256;                                           \
            if (idx < BE4) {                                                   \
                int r  = idx / (BN_ / 4);                                      \
                int c4 = idx % (BN_ / 4);                                      \
                int gc = c4 * 4;                                               \
                if (gc + 4 > N) gc = N - 4;                                    \
                cp16(smem_u32(&Bsp[st][r * LDB + c4 * 4]),                     \
                     &B[(size_t)(k0 + r) * N + gc]);                           \
            }                                                                  \
        }                                                                      \
        CP_COMMIT();                                                           \
    } while (0)

    PREFETCH(0, 0);

    for (int t = 0; t < T; t++) {
        CP_WAIT0();
        __syncthreads();
        if (t + 1 < T)
            PREFETCH(t + 1, (t + 1) & 1);
        const int st = t & 1;
#pragma unroll
        for (int kk = 0; kk < BK; kk += 8) {
            wmma::fragment<wmma::matrix_a, 16, 16, 8, wmma::precision::tf32, wmma::row_major> a[MF];
            wmma::fragment<wmma::matrix_b, 16, 16, 8, wmma::precision::tf32, wmma::row_major> b[NF];
#pragma unroll
            for (int i = 0; i < MF; i++) {
                wmma::load_matrix_sync(a[i], &Asp[st][(wm * WTM + i * 16) * LDA + kk], LDA);
                if (CONVA) {
#pragma unroll
                    for (int e = 0; e < a[i].num_elements; e++)
                        a[i].x[e] = wmma::__float_to_tf32(a[i].x[e]);
                }
            }
#pragma unroll
            for (int j = 0; j < NF; j++)
                wmma::load_matrix_sync(b[j], &Bsp[st][kk * LDB + wn * WTN + j * 16], LDB);
#pragma unroll
            for (int i = 0; i < MF; i++)
#pragma unroll
                for (int j = 0; j < NF; j++)
                    wmma::mma_sync(acc[i][j], a[i], b[j], acc[i][j]);
        }
        __syncthreads();
    }
#undef PREFETCH

    // ---- Epilogue: C store (bf16 or fp32) + fused el/er from registers ----
    float* stage = pool;                    // 8 warps * 16*20 = 2560
    float* alsm  = pool + 8 * 16 * 20;      // BN_
    float* arsm  = alsm + BN_;              // BN_
    float* bufl  = arsm + BN_;              // BM
    float* bufr  = bufl + BM;               // BM

    for (int i = tid; i < BN_; i += 256) {
        alsm[i] = (i < N) ? alv[i] : 0.f;
        arsm[i] = (i < N) ? arv[i] : 0.f;
    }
    __syncthreads();

    const int row_l = lane & 15;
    const int half  = lane >> 4;
    float* mystage = stage + warp * (16 * 20);

    float hel[MF][HEADS], her[MF][HEADS];
#pragma unroll
    for (int i = 0; i < MF; i++)
#pragma unroll
        for (int h = 0; h < HEADS; h++) { hel[i][h] = 0.f; her[i][h] = 0.f; }

#pragma unroll
    for (int i = 0; i < MF; i++) {
        const int row0 = brow + wm * WTM + i * 16;
#pragma unroll
        for (int j = 0; j < NF; j++) {
            const int col0 = wn * WTN + j * 16;
            const bool inb = (row0 + 16 <= M) && (col0 + 16 <= ldc);
            if (!STOREBF && inb)
                wmma::store_matrix_sync(&C[(size_t)row0 * ldc + col0], acc[i][j],
                                        ldc, wmma::mem_row_major);
            wmma::store_matrix_sync(mystage, acc[i][j], 20, wmma::mem_row_major);
            __syncwarp();
            float f[8];
            float sl = 0.f, sr = 0.f;
#pragma unroll
            for (int c = 0; c < 8; c++) {
                f[c] = mystage[row_l * 20 + half * 8 + c];
                sl = fmaf(f[c], alsm[col0 + half * 8 + c], sl);
                sr = fmaf(f[c], arsm[col0 + half * 8 + c], sr);
            }
            if (STOREBF && inb) {
                __nv_bfloat162 p[4];
#pragma unroll
                for (int c = 0; c < 4; c++)
                    p[c] = __nv_bfloat162(__float2bfloat16_rn(f[2 * c]),
                                          __float2bfloat16_rn(f[2 * c + 1]));
                *(uint4*)&Cbf[(size_t)(row0 + row_l) * ldc + col0 + half * 8] =
                    *(const uint4*)p;
            }
            __syncwarp();
            const int hd = col0 / DHEAD;
#pragma unroll
            for (int h = 0; h < HEADS; h++)
                if (hd == h) { hel[i][h] += sl; her[i][h] += sr; }
        }
    }

#pragma unroll
    for (int i = 0; i < MF; i++)
#pragma unroll
        for (int h = 0; h < HEADS; h++) {
            hel[i][h] += __shfl_xor_sync(0xffffffffu, hel[i][h], 16);
            her[i][h] += __shfl_xor_sync(0xffffffffu, her[i][h], 16);
        }

#pragma unroll
    for (int i = 0; i < MF; i++) {
        const int grow = brow + wm * WTM + i * 16 + row_l;
        const bool w = (half == 0) && (grow < M);
        if (WN_ == 1) {
            if (w) {
#pragma unroll
                for (int h = 0; h < HEADS; h++) {
                    el[grow * HEADS + h] = hel[i][h];
                    er[grow * HEADS + h] = her[i][h];
                }
            }
        } else {
            if (w && wn == 0) {
                el[grow * HEADS + 0] = hel[i][0];
                er[grow * HEADS + 0] = her[i][0];
                bufl[grow - brow] = hel[i][1];
                bufr[grow - brow] = her[i][1];
            }
        }
    }
    if (WN_ > 1) {
        __syncthreads();
#pragma unroll
        for (int i = 0; i < MF; i++) {
            const int grow = brow + wm * WTM + i * 16 + row_l;
            const bool w = (half == 0) && (grow < M);
            if (w && wn == 1) {
                el[grow * HEADS + 1] = bufl[grow - brow] + hel[i][1];
                er[grow * HEADS + 1] = bufr[grow - brow] + her[i][1];
                el[grow * HEADS + 2] = hel[i][2];
                er[grow * HEADS + 2] = her[i][2];
            }
        }
    }
}

// ---------------------------------------------------------------------------
// gat_softmax: warp per dst. Max-shifted softmax; writes normalized alpha.
// ---------------------------------------------------------------------------
__device__ __forceinline__ float leaky02(float v) {
    return v > 0.f ? v : 0.2f * v;
}

template <int H>
__global__ __launch_bounds__(256) void gat_softmax(
    const float* __restrict__ el, const float* __restrict__ er,
    const int* __restrict__ src, const int* __restrict__ rp,
    float* __restrict__ alpha, int n_dst)
{
    const int gw = (blockIdx.x * blockDim.x + threadIdx.x) >> 5;
    if (gw >= n_dst) return;
    const int lane = threadIdx.x & 31;
    const int d = gw;
    const int start = rp[d];
    const int end   = rp[d + 1];

    float er_d[H];
#pragma unroll
    for (int hh = 0; hh < H; hh++) er_d[hh] = er[d * H + hh];

    float v0[H], m[H];
#pragma unroll
    for (int hh = 0; hh < H; hh++) { v0[hh] = 0.f; m[hh] = -INFINITY; }
    {
        int e = start + lane;
        if (e < end) {
            int sn = src[e];
#pragma unroll
            for (int hh = 0; hh < H; hh++) {
                v0[hh] = leaky02(el[sn * H + hh] + er_d[hh]);
                m[hh]  = v0[hh];
            }
        }
    }
    for (int e = start + 32 + lane; e < end; e += 32) {
        int sn = src[e];
#pragma unroll
        for (int hh = 0; hh < H; hh++)
            m[hh] = fmaxf(m[hh], leaky02(el[sn * H + hh] + er_d[hh]));
    }
#pragma unroll
    for (int hh = 0; hh < H; hh++)
#pragma unroll
        for (int o = 16; o; o >>= 1)
            m[hh] = fmaxf(m[hh], __shfl_xor_sync(0xffffffffu, m[hh], o));

    float w0[H], s[H];
#pragma unroll
    for (int hh = 0; hh < H; hh++) { s[hh] = 0.f; w0[hh] = 0.f; }
    if (start + lane < end) {
#pragma unroll
        for (int hh = 0; hh < H; hh++) {
            w0[hh] = __expf(v0[hh] - m[hh]);
            s[hh]  = w0[hh];
        }
    }
    for (int e = start + 32 + lane; e < end; e += 32) {
        int sn = src[e];
#pragma unroll
        for (int hh = 0; hh < H; hh++)
            s[hh] += __expf(leaky02(el[sn * H + hh] + er_d[hh]) - m[hh]);
    }
#pragma unroll
    for (int hh = 0; hh < H; hh++)
#pragma unroll
        for (int o = 16; o; o >>= 1)
            s[hh] += __shfl_xor_sync(0xffffffffu, s[hh], o);
    float inv[H];
#pragma unroll
    for (int hh = 0; hh < H; hh++)
        inv[hh] = (s[hh] > 0.f) ? 1.0f / s[hh] : 0.f;

    if (start + lane < end) {
        int e = start + lane;
#pragma unroll
        for (int hh = 0; hh < H; hh++)
            alpha[(size_t)e * H + hh] = w0[hh] * inv[hh];
    }
    for (int e = start + 32 + lane; e < end; e += 32) {
        int sn = src[e];
#pragma unroll
        for (int hh = 0; hh < H; hh++)
            alpha[(size_t)e * H + hh] =
                __expf(leaky02(el[sn * H + hh] + er_d[hh]) - m[hh]) * inv[hh];
    }
}

// ---------------------------------------------------------------------------
// gat_gather_bf: warp per dst over bf16 features (H=3, D=64, stride 192).
// Lane j<24 owns one 8-element (16B) chunk; per-edge bytes HALVED vs fp32.
// Unroll 2 edges (proven sweet spot). Output fp32 + tf32 RN round.
// ---------------------------------------------------------------------------
template <bool RELU>
__global__ __launch_bounds__(256) void gat_gather_bf(
    const __nv_bfloat16* __restrict__ h, const float* __restrict__ alpha,
    const int* __restrict__ src, const int* __restrict__ rp,
    float* __restrict__ out, int n_dst)
{
    constexpr int HD = 192;
    constexpr int CH = HD / 8;    // 24 chunks

    const int gw = (blockIdx.x * blockDim.x + threadIdx.x) >> 5;
    if (gw >= n_dst) return;
    const int lane = threadIdx.x & 31;
    const int d = gw;
    const int start = rp[d];
    const int end   = rp[d + 1];

    const int j    = lane;
    const int head = (j < CH) ? (j * 8) / DH : 0;
    const bool act = (j < CH);

    float acc[8];
#pragma unroll
    for (int q = 0; q < 8; q++) acc[q] = 0.f;

    int e = start;
    for (; e + 2 <= end; e += 2) {
        const int sn0 = __ldg(&src[e]);
        const int sn1 = __ldg(&src[e + 1]);
        if (act) {
            const float a0 = __ldg(&alpha[(size_t)e * NHEAD + head]);
            const float a1 = __ldg(&alpha[(size_t)(e + 1) * NHEAD + head]);
            const uint4 u0 = *((const uint4*)(h + (size_t)sn0 * HD) + j);
            const uint4 u1 = *((const uint4*)(h + (size_t)sn1 * HD) + j);
            const __nv_bfloat162* p0 = (const __nv_bfloat162*)&u0;
            const __nv_bfloat162* p1 = (const __nv_bfloat162*)&u1;
#pragma unroll
            for (int k = 0; k < 4; k++) {
                float2 f0 = __bfloat1622float2(p0[k]);
                float2 f1 = __bfloat1622float2(p1[k]);
                acc[2 * k]     = fmaf(f0.x, a0, acc[2 * k]);
                acc[2 * k + 1] = fmaf(f0.y, a0, acc[2 * k + 1]);
                acc[2 * k]     = fmaf(f1.x, a1, acc[2 * k]);
                acc[2 * k + 1] = fmaf(f1.y, a1, acc[2 * k + 1]);
            }
        }
    }
    if (e < end) {
        const int sn0 = __ldg(&src[e]);
        if (act) {
            const float a0 = __ldg(&alpha[(size_t)e * NHEAD + head]);
            const uint4 u0 = *((const uint4*)(h + (size_t)sn0 * HD) + j);
            const __nv_bfloat162* p0 = (const __nv_bfloat162*)&u0;
#pragma unroll
            for (int k = 0; k < 4; k++) {
                float2 f0 = __bfloat1622float2(p0[k]);
                acc[2 * k]     = fmaf(f0.x, a0, acc[2 * k]);
                acc[2 * k + 1] = fmaf(f0.y, a0, acc[2 * k + 1]);
            }
        }
    }

    if (act) {
#pragma unroll
        for (int q = 0; q < 8; q++) {
            if (RELU) acc[q] = fmaxf(acc[q], 0.f);
            acc[q] = wmma::__float_to_tf32(acc[q]);   // feeds next GEMM A
        }
        float4* op = (float4*)(out + (size_t)d * HD + j * 8);
        op[0] = make_float4(acc[0], acc[1], acc[2], acc[3]);
        op[1] = make_float4(acc[4], acc[5], acc[6], acc[7]);
    }
}

// ---------------------------------------------------------------------------
// gat_gather (fp32): layer 2 only (H=1, D=40, stride 48). R10-proven.
// ---------------------------------------------------------------------------
template <int H, int D, int STRIDE, bool RELU, bool TF32OUT>
__global__ __launch_bounds__(256) void gat_gather(
    const float* __restrict__ h, const float* __restrict__ alpha,
    const int* __restrict__ src, const int* __restrict__ rp,
    float* __restrict__ out, int n_dst)
{
    constexpr int HD  = H * D;
    constexpr int HD4 = HD / 4;
    constexpr int NJ  = (HD4 + 31) / 32;

    const int gw = (blockIdx.x * blockDim.x + threadIdx.x) >> 5;
    if (gw >= n_dst) return;
    const int lane = threadIdx.x & 31;
    const int d = gw;
    const int start = rp[d];
    const int end   = rp[d + 1];

    int headj[NJ];
#pragma unroll
    for (int jj = 0; jj < NJ; jj++) {
        int j = lane + jj * 32;
        int hh = (j * 4) / D;
        headj[jj] = hh < H ? hh : H - 1;
    }

    float4 facc[NJ];
#pragma unroll
    for (int jj = 0; jj < NJ; jj++) facc[jj] = make_float4(0.f, 0.f, 0.f, 0.f);

    int e = start;
    for (; e + 2 <= end; e += 2) {
        const int sn0 = __ldg(&src[e]);
        const int sn1 = __ldg(&src[e + 1]);
        float a0[NJ], a1[NJ];
#pragma unroll
        for (int jj = 0; jj < NJ; jj++) {
            a0[jj] = __ldg(&alpha[(size_t)e * H + headj[jj]]);
            a1[jj] = __ldg(&alpha[(size_t)(e + 1) * H + headj[jj]]);
        }
        const float4* hp0 = (const float4*)(h + (size_t)sn0 * STRIDE);
        const float4* hp1 = (const float4*)(h + (size_t)sn1 * STRIDE);
#pragma unroll
        for (int jj = 0; jj < NJ; jj++) {
            int j = lane + jj * 32;
            if (j < HD4) {
                float4 v0 = hp0[j];
                float4 v1 = hp1[j];
                facc[jj].x = fmaf(v0.x, a0[jj], facc[jj].x);
                facc[jj].y = fmaf(v0.y, a0[jj], facc[jj].y);
                facc[jj].z = fmaf(v0.z, a0[jj], facc[jj].z);
                facc[jj].w = fmaf(v0.w, a0[jj], facc[jj].w);
                facc[jj].x = fmaf(v1.x, a1[jj], facc[jj].x);
                facc[jj].y = fmaf(v1.y, a1[jj], facc[jj].y);
                facc[jj].z = fmaf(v1.z, a1[jj], facc[jj].z);
                facc[jj].w = fmaf(v1.w, a1[jj], facc[jj].w);
            }
        }
    }
    if (e < end) {
        const int sn0 = __ldg(&src[e]);
        const float4* hp0 = (const float4*)(h + (size_t)sn0 * STRIDE);
#pragma unroll
        for (int jj = 0; jj < NJ; jj++) {
            int j = lane + jj * 32;
            if (j < HD4) {
                float a = __ldg(&alpha[(size_t)e * H + headj[jj]]);
                float4 v = hp0[j];
                facc[jj].x = fmaf(v.x, a, facc[jj].x);
                facc[jj].y = fmaf(v.y, a, facc[jj].y);
                facc[jj].z = fmaf(v.z, a, facc[jj].z);
                facc[jj].w = fmaf(v.w, a, facc[jj].w);
            }
        }
    }

#pragma unroll
    for (int jj = 0; jj < NJ; jj++) {
        int j = lane + jj * 32;
        if (j < HD4) {
            float4 r = facc[jj];
            if (RELU) {
                r.x = fmaxf(r.x, 0.f); r.y = fmaxf(r.y, 0.f);
                r.z = fmaxf(r.z, 0.f); r.w = fmaxf(r.w, 0.f);
            }
            if (TF32OUT) {
                r.x = wmma::__float_to_tf32(r.x);
                r.y = wmma::__float_to_tf32(r.y);
                r.z = wmma::__float_to_tf32(r.z);
                r.w = wmma::__float_to_tf32(r.w);
            }
            ((float4*)(out + (size_t)d * HD))[j] = r;
        }
    }
}

// ---------------------------------------------------------------------------
// Launch
// ---------------------------------------------------------------------------
static inline int ceil_div(int a, int b) { return (a + b - 1) / b; }

extern "C" void kernel_launch(void* const* d_in, const int* in_sizes, int n_in,
                              void* d_out, int out_size)
{
    const float* x    = (const float*)d_in[0];
    const int*   src0 = (const int*)  d_in[1];
    const int*   dst0 = (const int*)  d_in[2];
    const int*   src1 = (const int*)  d_in[3];
    const int*   dst1 = (const int*)  d_in[4];
    const int*   src2 = (const int*)  d_in[5];
    const int*   dst2 = (const int*)  d_in[6];
    const float* W0   = (const float*)d_in[7];
    const float* al0  = (const float*)d_in[8];
    const float* ar0  = (const float*)d_in[9];
    const float* W1   = (const float*)d_in[10];
    const float* al1  = (const float*)d_in[11];
    const float* ar1  = (const float*)d_in[12];
    const float* W2   = (const float*)d_in[13];
    const float* al2  = (const float*)d_in[14];
    const float* ar2  = (const float*)d_in[15];
    float* out = (float*)d_out;

    const int E0 = in_sizes[1];
    const int E1 = in_sizes[3];
    const int E2 = in_sizes[5];

    float *hbuf, *obuf, *el, *er, *alpha, *w0r, *w1r, *w2r;
    __nv_bfloat16* hbf;
    int *rp0, *rp1, *rp2;
    cudaGetSymbolAddress((void**)&hbf,   g_hbf);
    cudaGetSymbolAddress((void**)&hbuf,  g_hbuf);
    cudaGetSymbolAddress((void**)&obuf,  g_obuf);
    cudaGetSymbolAddress((void**)&el,    g_el);
    cudaGetSymbolAddress((void**)&er,    g_er);
    cudaGetSymbolAddress((void**)&alpha, g_alpha);
    cudaGetSymbolAddress((void**)&w0r,   g_W0r);
    cudaGetSymbolAddress((void**)&w1r,   g_W1r);
    cudaGetSymbolAddress((void**)&w2r,   g_W2r);
    cudaGetSymbolAddress((void**)&rp0,   g_rp0);
    cudaGetSymbolAddress((void**)&rp1,   g_rp1);
    cudaGetSymbolAddress((void**)&rp2,   g_rp2);

    round_w_kernel<<<ceil_div(FIN * FMID, 256), 256>>>(W0, W1, W2, w0r, w1r, w2r);
    rowptr_all<<<ceil_div(E0 + E1 + E2, 256), 256>>>(dst0, E0, dst1, E1, dst2, E2,
                                                     rp0, rp1, rp2);

    // ---------------- Layer 0: 200000x256 @ 256x192, bf16 features -------
    {
        gemm_fused<FMID, 4, 2, true, DH, NHEAD, true><<<ceil_div(NODES0, 128), 256>>>(
            x, w0r, nullptr, hbf, NODES0, FMID, FIN, FMID, al0, ar0, el, er);
        gat_softmax<NHEAD><<<ceil_div(NODES1, 8), 256>>>(el, er, src0, rp0, alpha, NODES1);
        gat_gather_bf<true><<<ceil_div(NODES1, 8), 256>>>(
            hbf, alpha, src0, rp0, obuf, NODES1);
    }

    // ---------------- Layer 1: 100000x192 @ 192x192, bf16 features -------
    {
        gemm_fused<FMID, 4, 2, false, DH, NHEAD, true><<<ceil_div(NODES1, 128), 256>>>(
            obuf, w1r, nullptr, hbf, NODES1, FMID, FMID, FMID, al1, ar1, el, er);
        gat_softmax<NHEAD><<<ceil_div(NODES2, 8), 256>>>(el, er, src1, rp1, alpha, NODES2);
        gat_gather_bf<true><<<ceil_div(NODES2, 8), 256>>>(
            hbf, alpha, src1, rp1, obuf, NODES2);
    }

    // ---------------- Layer 2: 50000x192 @ 192x40 (fp32, padded ldc=48) --
    {
        gemm_fused<COUT_PAD, 8, 1, false, 64, 1, false><<<ceil_div(NODES2, 128), 256>>>(
            obuf, w2r, hbuf, nullptr, NODES2, COUT, FMID, COUT_PAD, al2, ar2, el, er);
        gat_softmax<1><<<ceil_div(NODES3, 8), 256>>>(el, er, src2, rp2, alpha, NODES3);
        gat_gather<1, COUT, COUT_PAD, false, false><<<ceil_div(NODES3, 8), 256>>>(
            hbuf, alpha, src2, rp2, out, NODES3);
    }
}